// round 1
// baseline (speedup 1.0000x reference)
#include <cuda_runtime.h>
#include <cuda_pipeline.h>
#include <math.h>

#define BB    32
#define TT    2048
#define DD    128
#define FF    16
#define SS    64
#define RR    64
#define STATE 1024
#define TWO_PI 6.28318530717958647692f

// Scratch (allocation-free rule: __device__ globals)
__device__ float g_states[BB * TT * STATE]; // 256 MB: state after each step, row = b*T + t
__device__ float g_U[TT * SS * RR];         // 32 MB: U_t[s,r] = sum_f c_f(t) * Wr[f*S+s, r]

__device__ __forceinline__ float gelu_exact(float v) { return v * normcdff(v); }

// ---------------------------------------------------------------------------
// Kernel A: precompute U_t for all t (data independent of the recurrence)
// ---------------------------------------------------------------------------
__global__ void precompute_U(const float* __restrict__ Wr,
                             const float* __restrict__ phases) {
    int t = blockIdx.x + 1;               // t = 1..T
    __shared__ float c[FF];
    if (threadIdx.x < FF) {
        float f = (float)threadIdx.x;
        float ang = (TWO_PI / (float)TT) * (float)t * f + TWO_PI * phases[threadIdx.x];
        c[threadIdx.x] = cosf(ang) * (1.0f / (float)TT);
    }
    __syncthreads();
    float* Udst = g_U + (size_t)(t - 1) * (SS * RR);
    for (int idx = threadIdx.x; idx < SS * RR; idx += blockDim.x) {
        int s = idx >> 6, r = idx & 63;
        float acc = 0.f;
#pragma unroll
        for (int f = 0; f < FF; ++f)
            acc += c[f] * Wr[(f * SS + s) * RR + r];
        Udst[idx] = acc;
    }
}

// ---------------------------------------------------------------------------
// Kernel B: the sequential recurrence. One CTA per batch, 256 threads.
// Maintains P = state @ Wr incrementally:  P' = (P - P0) + stats @ U_t,
// P0' = c0(t) * (stats @ Wr0). Writes state after every step to g_states.
// ---------------------------------------------------------------------------
__global__ __launch_bounds__(256, 1)
void fru_recurrence(const float* __restrict__ x,
                    const float* __restrict__ Ws,
                    const float* __restrict__ bs,
                    const float* __restrict__ br,
                    const float* __restrict__ Wr,
                    const float* __restrict__ phases) {
    __shared__ __align__(16) float sU[2][SS * RR];   // 32 KB, double buffered
    __shared__ __align__(16) float sx[2][DD];        // x_t double buffered
    __shared__ float sstate[STATE];
    __shared__ float sP[RR], sP0[RR], sstats[SS], srecur[RR];
    __shared__ float sredA[4 * 64], sredB[4 * 64];
    __shared__ float sc[FF], sph2[FF], sbr[RR], sbs[SS];

    const int tid  = threadIdx.x;
    const int lane = tid & 63;   // s (step2) or r (step3)
    const int grp  = tid >> 6;   // 0..3
    const int b    = blockIdx.x;

    // Register-resident constant weights (reused all 2048 steps)
    float wsr[48];               // Ws[(grp*48+kk)*64 + lane]
#pragma unroll
    for (int kk = 0; kk < 48; ++kk)
        wsr[kk] = Ws[(grp * 48 + kk) * SS + lane];
    float wr0r[16];              // Wr0 rows grp*16+ss, col lane
#pragma unroll
    for (int ss = 0; ss < 16; ++ss)
        wr0r[ss] = Wr[(grp * 16 + ss) * RR + lane];

    // Init
    for (int i = tid; i < STATE; i += 256) sstate[i] = 0.f;
    if (tid < RR) { sP[tid] = 0.f; sP0[tid] = 0.f; sbr[tid] = br[tid]; }
    if (tid < SS) { sbs[tid] = bs[tid]; }
    if (tid < FF) { sph2[tid] = TWO_PI * phases[tid]; }

    // Prefetch t=1 into buffer 0
    {
        const float* Usrc = g_U;  // t=1
#pragma unroll
        for (int q = 0; q < 4; ++q) {
            int i = tid + q * 256;
            __pipeline_memcpy_async(&sU[0][i * 4], &Usrc[i * 4], 16);
        }
        if (tid < 32)
            __pipeline_memcpy_async(&sx[0][tid * 4],
                                    x + ((size_t)b * TT) * DD + tid * 4, 16);
        __pipeline_commit();
    }

    const float invL  = 1.0f / (float)TT;
    const float wbase = TWO_PI / (float)TT;

    for (int t = 1; t <= TT; ++t) {
        const int cur = (t - 1) & 1;
        const int nxt = cur ^ 1;

        __pipeline_wait_prior(0);
        __syncthreads();                         // BAR0: U_t / x_t visible

        if (t < TT) {                            // prefetch t+1
            const float* Usrc = g_U + (size_t)t * (SS * RR);
#pragma unroll
            for (int q = 0; q < 4; ++q) {
                int i = tid + q * 256;
                __pipeline_memcpy_async(&sU[nxt][i * 4], &Usrc[i * 4], 16);
            }
            if (tid < 32)
                __pipeline_memcpy_async(&sx[nxt][tid * 4],
                                        x + ((size_t)b * TT + t) * DD + tid * 4, 16);
            __pipeline_commit();
        }

        // c_f(t) and recur = gelu(P + br)
        if (tid < FF) {
            float fv = (float)tid;
            sc[tid] = invL * cosf(wbase * (float)t * fv + sph2[tid]);
        }
        if (tid < RR) {
            float v = sP[tid] + sbr[tid];
            srecur[tid] = gelu_exact(v);
        }
        __syncthreads();                         // BAR1

        // step2: stats_pre[s] partials over k-range (48 per group)
        {
            float a0 = 0.f, a1 = 0.f, a2 = 0.f, a3 = 0.f;
            const int k0 = grp * 48;
#pragma unroll
            for (int kk = 0; kk < 48; ++kk) {
                int k = k0 + kk;
                float v = (k < DD) ? sx[cur][k] : srecur[k - DD];
                float p = v * wsr[kk];
                if ((kk & 3) == 0) a0 += p;
                else if ((kk & 3) == 1) a1 += p;
                else if ((kk & 3) == 2) a2 += p;
                else a3 += p;
            }
            sredA[grp * 64 + lane] = (a0 + a1) + (a2 + a3);
        }
        __syncthreads();                         // BAR2

        if (tid < SS) {
            float v = sredA[tid] + sredA[64 + tid] + sredA[128 + tid] +
                      sredA[192 + tid] + sbs[tid];
            sstats[tid] = gelu_exact(v);
        }
        __syncthreads();                         // BAR3

        // step4: state update + store (thread-private element mapping)
        {
            const size_t outbase = ((size_t)b * TT + (t - 1)) * STATE;
#pragma unroll
            for (int q = 0; q < 4; ++q) {
                int i = tid + q * 256;
                int f = i >> 6, s = i & 63;
                float prev = (f == 0) ? 0.f : sstate[i];
                float ns = prev + sc[f] * sstats[s];
                sstate[i] = ns;
                g_states[outbase + i] = ns;
            }
        }

        // step3: P/P0 partials (after BAR3, redA free to reuse)
        {
            float a1 = 0.f, b1 = 0.f, a2 = 0.f, b2 = 0.f;
            const int s0 = grp * 16;
#pragma unroll
            for (int ss = 0; ss < 16; ++ss) {
                float sv = sstats[s0 + ss];
                float u  = sU[cur][(s0 + ss) * RR + lane];
                if (ss & 1) { a1 += sv * u; b1 += sv * wr0r[ss]; }
                else        { a2 += sv * u; b2 += sv * wr0r[ss]; }
            }
            sredA[grp * 64 + lane] = a1 + a2;
            sredB[grp * 64 + lane] = b1 + b2;
        }
        __syncthreads();                         // BAR4

        if (tid < RR) {
            float su = sredA[tid] + sredA[64 + tid] + sredA[128 + tid] + sredA[192 + tid];
            float sw = sredB[tid] + sredB[64 + tid] + sredB[128 + tid] + sredB[192 + tid];
            float np = sP[tid] - sP0[tid] + su;
            sP[tid]  = np;
            sP0[tid] = sc[0] * sw;
        }
    }
}

// ---------------------------------------------------------------------------
// Kernel C: out = gelu(states @ Wo + bo).  M=65536, N=1024, K=1024, fp32 SIMT.
// 128x128 tile, BK=8, 256 threads, 8x8 per thread.
// ---------------------------------------------------------------------------
#define BM 128
#define BN 128
#define BK 8

__global__ __launch_bounds__(256, 2)
void out_gemm(const float* __restrict__ Wo,
              const float* __restrict__ bo,
              float* __restrict__ out) {
    __shared__ float As[BK][BM + 4];   // transposed A tile, padded (row stride 132 = 33*16B)
    __shared__ float Bs[BK][BN];

    const int tid = threadIdx.x;
    const int tx = tid & 15;           // 0..15 (N)
    const int ty = tid >> 4;           // 0..15 (M)
    const int mBase = blockIdx.y * BM; // 0..65408
    const int nBase = blockIdx.x * BN; // 0..896

    const float* Aptr = g_states + (size_t)mBase * 1024;
    const float* Bptr = Wo + nBase;

    // load mapping
    const int aRow = tid >> 1;          // 0..127
    const int aCol = (tid & 1) * 4;     // 0 or 4
    const int bRow = tid >> 5;          // 0..7
    const int bCol = (tid & 31) * 4;    // 0..124

    float acc[8][8];
#pragma unroll
    for (int i = 0; i < 8; ++i)
#pragma unroll
        for (int j = 0; j < 8; ++j) acc[i][j] = 0.f;

    for (int k0 = 0; k0 < 1024; k0 += BK) {
        float4 av = *(const float4*)(Aptr + (size_t)aRow * 1024 + k0 + aCol);
        float4 bv = *(const float4*)(Bptr + (size_t)(k0 + bRow) * 1024 + bCol);
        __syncthreads();
        As[aCol + 0][aRow] = av.x;
        As[aCol + 1][aRow] = av.y;
        As[aCol + 2][aRow] = av.z;
        As[aCol + 3][aRow] = av.w;
        *(float4*)&Bs[bRow][bCol] = bv;
        __syncthreads();
#pragma unroll
        for (int kk = 0; kk < BK; ++kk) {
            float4 ra0 = *(const float4*)&As[kk][ty * 8];
            float4 ra1 = *(const float4*)&As[kk][ty * 8 + 4];
            float4 rb0 = *(const float4*)&Bs[kk][tx * 8];
            float4 rb1 = *(const float4*)&Bs[kk][tx * 8 + 4];
            float ra[8] = {ra0.x, ra0.y, ra0.z, ra0.w, ra1.x, ra1.y, ra1.z, ra1.w};
            float rb[8] = {rb0.x, rb0.y, rb0.z, rb0.w, rb1.x, rb1.y, rb1.z, rb1.w};
#pragma unroll
            for (int i = 0; i < 8; ++i)
#pragma unroll
                for (int j = 0; j < 8; ++j)
                    acc[i][j] += ra[i] * rb[j];
        }
    }

    // Epilogue: +bias, exact gelu, store
    float bofr[8];
#pragma unroll
    for (int j = 0; j < 8; ++j) bofr[j] = bo[nBase + tx * 8 + j];
#pragma unroll
    for (int i = 0; i < 8; ++i) {
        const size_t m = (size_t)(mBase + ty * 8 + i);
        float4 o0, o1;
        float v;
        v = acc[i][0] + bofr[0]; o0.x = gelu_exact(v);
        v = acc[i][1] + bofr[1]; o0.y = gelu_exact(v);
        v = acc[i][2] + bofr[2]; o0.z = gelu_exact(v);
        v = acc[i][3] + bofr[3]; o0.w = gelu_exact(v);
        v = acc[i][4] + bofr[4]; o1.x = gelu_exact(v);
        v = acc[i][5] + bofr[5]; o1.y = gelu_exact(v);
        v = acc[i][6] + bofr[6]; o1.z = gelu_exact(v);
        v = acc[i][7] + bofr[7]; o1.w = gelu_exact(v);
        *(float4*)(out + m * 1024 + nBase + tx * 8)     = o0;
        *(float4*)(out + m * 1024 + nBase + tx * 8 + 4) = o1;
    }
}

// ---------------------------------------------------------------------------
extern "C" void kernel_launch(void* const* d_in, const int* in_sizes, int n_in,
                              void* d_out, int out_size) {
    const float* x   = (const float*)d_in[0];  // (B,T,D)
    const float* Wr  = (const float*)d_in[1];  // (STATE,R)
    const float* br  = (const float*)d_in[2];  // (R,)
    const float* Ws  = (const float*)d_in[3];  // (D+R,S)
    const float* bs  = (const float*)d_in[4];  // (S,)
    const float* Wo  = (const float*)d_in[5];  // (STATE,STATE)
    const float* bo  = (const float*)d_in[6];  // (STATE,)
    const float* ph  = (const float*)d_in[7];  // (1,F,1)
    float* out = (float*)d_out;

    precompute_U<<<TT, 256>>>(Wr, ph);
    fru_recurrence<<<BB, 256>>>(x, Ws, bs, br, Wr, ph);
    out_gemm<<<dim3(1024 / BN, (BB * TT) / BM), 256>>>(Wo, bo, out);
}

// round 3
// speedup vs baseline: 1.4552x; 1.4552x over previous
#include <cuda_runtime.h>
#include <cuda_pipeline.h>
#include <cuda_bf16.h>
#include <math.h>
#include <stdint.h>

#define BB    32
#define TT    2048
#define DD    128
#define FF    16
#define SS    64
#define RR    64
#define STATE 1024
#define TWO_PI 6.28318530717958647692f

#define MTOT  (BB * TT)      // 65536 GEMM rows
#define KTOT  1024
#define NTOT  1024

// ---------------- scratch (__device__ globals; no allocation allowed) -------
__device__ float         g_U[TT * SS * RR];            // 32 MB
__device__ __nv_bfloat16 g_Ahi[(size_t)MTOT * KTOT];   // 128 MB  states hi
__device__ __nv_bfloat16 g_Alo[(size_t)MTOT * KTOT];   // 128 MB  states lo
__device__ __nv_bfloat16 g_Bhi[(size_t)NTOT * KTOT];   // 2 MB    Wo^T hi (N-major)
__device__ __nv_bfloat16 g_Blo[(size_t)NTOT * KTOT];   // 2 MB    Wo^T lo (N-major)

__device__ __forceinline__ float gelu_exact(float v) { return v * normcdff(v); }

__device__ __forceinline__ uint32_t smem_u32(const void* p) {
    uint32_t a;
    asm("{ .reg .u64 t; cvta.to.shared.u64 t, %1; cvt.u32.u64 %0, t; }" : "=r"(a) : "l"(p));
    return a;
}
__device__ __forceinline__ void ldsm4(uint32_t* r, uint32_t addr) {
    asm volatile("ldmatrix.sync.aligned.m8n8.x4.shared.b16 {%0,%1,%2,%3}, [%4];"
                 : "=r"(r[0]), "=r"(r[1]), "=r"(r[2]), "=r"(r[3]) : "r"(addr));
}
__device__ __forceinline__ void mma16816(float* c, const uint32_t* a, const uint32_t* b) {
    asm volatile(
        "mma.sync.aligned.m16n8k16.row.col.f32.bf16.bf16.f32 "
        "{%0,%1,%2,%3}, {%4,%5,%6,%7}, {%8,%9}, {%0,%1,%2,%3};"
        : "+f"(c[0]), "+f"(c[1]), "+f"(c[2]), "+f"(c[3])
        : "r"(a[0]), "r"(a[1]), "r"(a[2]), "r"(a[3]), "r"(b[0]), "r"(b[1]));
}

// ---------------------------------------------------------------------------
// Kernel A: precompute U_t[s,r] = sum_f c_f(t) Wr[f*S+s, r]
// ---------------------------------------------------------------------------
__global__ void precompute_U(const float* __restrict__ Wr,
                             const float* __restrict__ phases) {
    int t = blockIdx.x + 1;
    __shared__ float c[FF];
    if (threadIdx.x < FF) {
        float f = (float)threadIdx.x;
        float ang = (TWO_PI / (float)TT) * (float)t * f + TWO_PI * phases[threadIdx.x];
        c[threadIdx.x] = cosf(ang) * (1.0f / (float)TT);
    }
    __syncthreads();
    float* Udst = g_U + (size_t)(t - 1) * (SS * RR);
    for (int idx = threadIdx.x; idx < SS * RR; idx += blockDim.x) {
        int s = idx >> 6, r = idx & 63;
        float acc = 0.f;
#pragma unroll
        for (int f = 0; f < FF; ++f)
            acc += c[f] * Wr[(f * SS + s) * RR + r];
        Udst[idx] = acc;
    }
}

// ---------------------------------------------------------------------------
// Kernel A2: Wo^T hi/lo bf16 (tiled transpose; result is N-major)
// ---------------------------------------------------------------------------
__global__ void make_WoT(const float* __restrict__ Wo) {
    __shared__ float tile[32][33];
    const int tx = threadIdx.x, ty = threadIdx.y;
    const int gx = blockIdx.x * 32;   // n
    const int gy = blockIdx.y * 32;   // k
#pragma unroll
    for (int i = 0; i < 32; i += 8)
        tile[ty + i][tx] = Wo[(size_t)(gy + ty + i) * NTOT + gx + tx];
    __syncthreads();
#pragma unroll
    for (int i = 0; i < 32; i += 8) {
        float v = tile[tx][ty + i];                    // Wo[gy+tx][gx+ty+i]
        int n = gx + ty + i, k = gy + tx;
        __nv_bfloat16 h = __float2bfloat16(v);
        float lo = v - __bfloat162float(h);
        g_Bhi[(size_t)n * KTOT + k] = h;
        g_Blo[(size_t)n * KTOT + k] = __float2bfloat16(lo);
    }
}

// ---------------------------------------------------------------------------
// Kernel B: sequential recurrence; stores states as bf16 hi/lo
// ---------------------------------------------------------------------------
__global__ __launch_bounds__(256, 1)
void fru_recurrence(const float* __restrict__ x,
                    const float* __restrict__ Ws,
                    const float* __restrict__ bs,
                    const float* __restrict__ br,
                    const float* __restrict__ Wr,
                    const float* __restrict__ phases) {
    __shared__ __align__(16) float sU[2][SS * RR];
    __shared__ __align__(16) float sx[2][DD];
    __shared__ float sstate[STATE];
    __shared__ float sP[RR], sP0[RR], sstats[SS], srecur[RR];
    __shared__ float sredA[4 * 64], sredB[4 * 64];
    __shared__ float sc[FF], sph2[FF], sbr[RR], sbs[SS];

    const int tid  = threadIdx.x;
    const int lane = tid & 63;
    const int grp  = tid >> 6;
    const int b    = blockIdx.x;

    float wsr[48];
#pragma unroll
    for (int kk = 0; kk < 48; ++kk)
        wsr[kk] = Ws[(grp * 48 + kk) * SS + lane];
    float wr0r[16];
#pragma unroll
    for (int ss = 0; ss < 16; ++ss)
        wr0r[ss] = Wr[(grp * 16 + ss) * RR + lane];

    for (int i = tid; i < STATE; i += 256) sstate[i] = 0.f;
    if (tid < RR) { sP[tid] = 0.f; sP0[tid] = 0.f; sbr[tid] = br[tid]; }
    if (tid < SS) { sbs[tid] = bs[tid]; }
    if (tid < FF) { sph2[tid] = TWO_PI * phases[tid]; }

    {
        const float* Usrc = g_U;
#pragma unroll
        for (int q = 0; q < 4; ++q) {
            int i = tid + q * 256;
            __pipeline_memcpy_async(&sU[0][i * 4], &Usrc[i * 4], 16);
        }
        if (tid < 32)
            __pipeline_memcpy_async(&sx[0][tid * 4],
                                    x + ((size_t)b * TT) * DD + tid * 4, 16);
        __pipeline_commit();
    }

    const float invL  = 1.0f / (float)TT;
    const float wbase = TWO_PI / (float)TT;

    for (int t = 1; t <= TT; ++t) {
        const int cur = (t - 1) & 1;
        const int nxt = cur ^ 1;

        __pipeline_wait_prior(0);
        __syncthreads();

        if (t < TT) {
            const float* Usrc = g_U + (size_t)t * (SS * RR);
#pragma unroll
            for (int q = 0; q < 4; ++q) {
                int i = tid + q * 256;
                __pipeline_memcpy_async(&sU[nxt][i * 4], &Usrc[i * 4], 16);
            }
            if (tid < 32)
                __pipeline_memcpy_async(&sx[nxt][tid * 4],
                                        x + ((size_t)b * TT + t) * DD + tid * 4, 16);
            __pipeline_commit();
        }

        if (tid < FF) {
            float fv = (float)tid;
            sc[tid] = invL * cosf(wbase * (float)t * fv + sph2[tid]);
        }
        if (tid < RR) {
            float v = sP[tid] + sbr[tid];
            srecur[tid] = gelu_exact(v);
        }
        __syncthreads();

        {
            float a0 = 0.f, a1 = 0.f, a2 = 0.f, a3 = 0.f;
            const int k0 = grp * 48;
#pragma unroll
            for (int kk = 0; kk < 48; ++kk) {
                int k = k0 + kk;
                float v = (k < DD) ? sx[cur][k] : srecur[k - DD];
                float p = v * wsr[kk];
                if ((kk & 3) == 0) a0 += p;
                else if ((kk & 3) == 1) a1 += p;
                else if ((kk & 3) == 2) a2 += p;
                else a3 += p;
            }
            sredA[grp * 64 + lane] = (a0 + a1) + (a2 + a3);
        }
        __syncthreads();

        if (tid < SS) {
            float v = sredA[tid] + sredA[64 + tid] + sredA[128 + tid] +
                      sredA[192 + tid] + sbs[tid];
            sstats[tid] = gelu_exact(v);
        }
        __syncthreads();

        {
            const size_t outbase = ((size_t)b * TT + (t - 1)) * STATE;
#pragma unroll
            for (int q = 0; q < 4; ++q) {
                int i = tid + q * 256;
                int f = i >> 6, s = i & 63;
                float prev = (f == 0) ? 0.f : sstate[i];
                float ns = prev + sc[f] * sstats[s];
                sstate[i] = ns;
                __nv_bfloat16 h = __float2bfloat16(ns);
                g_Ahi[outbase + i] = h;
                g_Alo[outbase + i] = __float2bfloat16(ns - __bfloat162float(h));
            }
        }

        {
            float a1 = 0.f, b1 = 0.f, a2 = 0.f, b2 = 0.f;
            const int s0 = grp * 16;
#pragma unroll
            for (int ss = 0; ss < 16; ++ss) {
                float sv = sstats[s0 + ss];
                float u  = sU[cur][(s0 + ss) * RR + lane];
                if (ss & 1) { a1 += sv * u; b1 += sv * wr0r[ss]; }
                else        { a2 += sv * u; b2 += sv * wr0r[ss]; }
            }
            sredA[grp * 64 + lane] = a1 + a2;
            sredB[grp * 64 + lane] = b1 + b2;
        }
        __syncthreads();

        if (tid < RR) {
            float su = sredA[tid] + sredA[64 + tid] + sredA[128 + tid] + sredA[192 + tid];
            float sw = sredB[tid] + sredB[64 + tid] + sredB[128 + tid] + sredB[192 + tid];
            float np = sP[tid] - sP0[tid] + su;
            sP[tid]  = np;
            sP0[tid] = sc[0] * sw;
        }
    }
}

// ---------------------------------------------------------------------------
// Kernel C: out = gelu(states @ Wo + bo) via mma.sync bf16 split (HMMA).
// BM=128, BN=128, BK=32, 8 warps (4M x 2N), warp tile 32x64, 3-stage cp.async.
// D = Ahi*Bhi + Ahi*Blo + Alo*Bhi (fp32 accumulate in registers).
// ---------------------------------------------------------------------------
#define BM 128
#define BN 128
#define BKH 32
#define NITER (KTOT / BKH)     // 32
#define NSTAGE 3
#define ROWH 40                               // padded row stride in halves (80B)
#define BUFB (128 * ROWH * 2)                 // 10240 B per matrix buffer
#define STAGEB (4 * BUFB)                     // 40960 B per stage
#define GEMM_SMEM (NSTAGE * STAGEB)           // 122880 B

#define LOAD_STAGE(step) do {                                               \
    char* st = smem + ((step) % NSTAGE) * STAGEB;                           \
    const int k0_ = (step) * BKH;                                           \
    _Pragma("unroll")                                                       \
    for (int q = 0; q < 2; ++q) {                                           \
        int idx = tid + q * 256;                                            \
        int r = idx >> 2, cc = idx & 3;                                     \
        int doff = (r * ROWH + cc * 8) * 2;                                 \
        size_t so = (size_t)r * KTOT + k0_ + cc * 8;                        \
        __pipeline_memcpy_async(st + doff,            Ah + so, 16);         \
        __pipeline_memcpy_async(st + BUFB + doff,     Al + so, 16);         \
        __pipeline_memcpy_async(st + 2 * BUFB + doff, Bh + so, 16);         \
        __pipeline_memcpy_async(st + 3 * BUFB + doff, Bl + so, 16);         \
    }                                                                       \
    __pipeline_commit();                                                    \
} while (0)

__global__ __launch_bounds__(256, 1)
void out_gemm_mma(const float* __restrict__ bo, float* __restrict__ out) {
    extern __shared__ __align__(128) char smem[];
    const uint32_t sbase = smem_u32(smem);
    const int tid  = threadIdx.x;
    const int lane = tid & 31;
    const int wid  = tid >> 5;
    const int wm   = wid & 3;       // 0..3 (M)
    const int wn   = wid >> 2;      // 0..1 (N)
    const int mBase = blockIdx.y * BM;
    const int nBase = blockIdx.x * BN;

    const __nv_bfloat16* Ah = g_Ahi + (size_t)mBase * KTOT;
    const __nv_bfloat16* Al = g_Alo + (size_t)mBase * KTOT;
    const __nv_bfloat16* Bh = g_Bhi + (size_t)nBase * KTOT;
    const __nv_bfloat16* Bl = g_Blo + (size_t)nBase * KTOT;

    // ldmatrix per-lane base offsets (bytes within a buffer)
    const int q = lane >> 3;
    // A quadrants: q0:(m,k0) q1:(m+8,k0) q2:(m,k8) q3:(m+8,k8)
    const uint32_t aoff = ((wm * 32 + (q & 1) * 8 + (lane & 7)) * ROWH + (q >> 1) * 8) * 2;
    // B quadrants: q0:(n,k0) q1:(n,k8) q2:(n+8,k0) q3:(n+8,k8)
    const uint32_t boff = ((wn * 64 + (q >> 1) * 8 + (lane & 7)) * ROWH + (q & 1) * 8) * 2;

    float acc[2][8][4];
#pragma unroll
    for (int i = 0; i < 2; ++i)
#pragma unroll
        for (int j = 0; j < 8; ++j)
#pragma unroll
            for (int v = 0; v < 4; ++v) acc[i][j][v] = 0.f;

    LOAD_STAGE(0);
    LOAD_STAGE(1);

    for (int i = 0; i < NITER; ++i) {
        if (i < NITER - 1) __pipeline_wait_prior(1);
        else               __pipeline_wait_prior(0);
        __syncthreads();
        if (i + 2 < NITER) LOAD_STAGE(i + 2);

        const uint32_t sb = sbase + (uint32_t)(i % NSTAGE) * STAGEB;
#pragma unroll
        for (int ks = 0; ks < 2; ++ks) {
            uint32_t ahi[2][4], alo[2][4];
            ldsm4(ahi[0], sb + aoff + ks * 32);
            ldsm4(ahi[1], sb + aoff + 16 * ROWH * 2 + ks * 32);
            ldsm4(alo[0], sb + BUFB + aoff + ks * 32);
            ldsm4(alo[1], sb + BUFB + aoff + 16 * ROWH * 2 + ks * 32);
#pragma unroll
            for (int nt = 0; nt < 4; ++nt) {
                uint32_t bhi[4], blo[4];
                ldsm4(bhi, sb + 2 * BUFB + boff + nt * 16 * ROWH * 2 + ks * 32);
                ldsm4(blo, sb + 3 * BUFB + boff + nt * 16 * ROWH * 2 + ks * 32);
#pragma unroll
                for (int mt = 0; mt < 2; ++mt) {
#pragma unroll
                    for (int sub = 0; sub < 2; ++sub) {
                        float* c = acc[mt][nt * 2 + sub];
                        mma16816(c, ahi[mt], bhi + 2 * sub);
                        mma16816(c, ahi[mt], blo + 2 * sub);
                        mma16816(c, alo[mt], bhi + 2 * sub);
                    }
                }
            }
        }
    }

    // Epilogue: +bias, exact gelu, store float2 pairs
    const int mrow = lane >> 2;
    const int ncol = (lane & 3) * 2;
#pragma unroll
    for (int mt = 0; mt < 2; ++mt) {
        const int m0 = mBase + wm * 32 + mt * 16 + mrow;
#pragma unroll
        for (int nt8 = 0; nt8 < 8; ++nt8) {
            const int n0 = nBase + wn * 64 + nt8 * 8 + ncol;
            const float b0 = __ldg(bo + n0), b1 = __ldg(bo + n0 + 1);
            const float* c = acc[mt][nt8];
            float2 v0 = {gelu_exact(c[0] + b0), gelu_exact(c[1] + b1)};
            float2 v1 = {gelu_exact(c[2] + b0), gelu_exact(c[3] + b1)};
            *(float2*)(out + (size_t)m0 * NTOT + n0)       = v0;
            *(float2*)(out + (size_t)(m0 + 8) * NTOT + n0) = v1;
        }
    }
}

// ---------------------------------------------------------------------------
extern "C" void kernel_launch(void* const* d_in, const int* in_sizes, int n_in,
                              void* d_out, int out_size) {
    const float* x   = (const float*)d_in[0];  // (B,T,D)
    const float* Wr  = (const float*)d_in[1];  // (STATE,R)
    const float* br  = (const float*)d_in[2];  // (R,)
    const float* Ws  = (const float*)d_in[3];  // (D+R,S)
    const float* bs  = (const float*)d_in[4];  // (S,)
    const float* Wo  = (const float*)d_in[5];  // (STATE,STATE)
    const float* bo  = (const float*)d_in[6];  // (STATE,)
    const float* ph  = (const float*)d_in[7];  // (1,F,1)
    float* out = (float*)d_out;

    cudaFuncSetAttribute(out_gemm_mma, cudaFuncAttributeMaxDynamicSharedMemorySize, GEMM_SMEM);

    precompute_U<<<TT, 256>>>(Wr, ph);
    make_WoT<<<dim3(32, 32), dim3(32, 8)>>>(Wo);
    fru_recurrence<<<BB, 256>>>(x, Ws, bs, br, Wr, ph);
    out_gemm_mma<<<dim3(NTOT / BN, MTOT / BM), 256, GEMM_SMEM>>>(bo, out);
}

// round 4
// speedup vs baseline: 1.5604x; 1.0723x over previous
#include <cuda_runtime.h>
#include <cuda_pipeline.h>
#include <cuda_bf16.h>
#include <math.h>
#include <stdint.h>

#define BB    32
#define TT    2048
#define DD    128
#define FF    16
#define SS    64
#define RR    64
#define STATE 1024
#define TWO_PI 6.28318530717958647692f

#define MTOT  (BB * TT)      // 65536 GEMM rows
#define KTOT  1024
#define NTOT  1024

// ---------------- scratch (__device__ globals; no allocation allowed) -------
__device__ float         g_U[TT * SS * RR];            // 32 MB
__device__ __nv_bfloat16 g_Ahi[(size_t)MTOT * KTOT];   // 128 MB  states hi
__device__ __nv_bfloat16 g_Alo[(size_t)MTOT * KTOT];   // 128 MB  states lo
__device__ __nv_bfloat16 g_Bhi[(size_t)NTOT * KTOT];   // 2 MB    Wo^T hi (N-major)
__device__ __nv_bfloat16 g_Blo[(size_t)NTOT * KTOT];   // 2 MB    Wo^T lo (N-major)

__device__ __forceinline__ float gelu_exact(float v) { return v * normcdff(v); }

__device__ __forceinline__ uint32_t smem_u32(const void* p) {
    uint32_t a;
    asm("{ .reg .u64 t; cvta.to.shared.u64 t, %1; cvt.u32.u64 %0, t; }" : "=r"(a) : "l"(p));
    return a;
}
__device__ __forceinline__ void ldsm4(uint32_t* r, uint32_t addr) {
    asm volatile("ldmatrix.sync.aligned.m8n8.x4.shared.b16 {%0,%1,%2,%3}, [%4];"
                 : "=r"(r[0]), "=r"(r[1]), "=r"(r[2]), "=r"(r[3]) : "r"(addr));
}
__device__ __forceinline__ void mma16816(float* c, const uint32_t* a, const uint32_t* b) {
    asm volatile(
        "mma.sync.aligned.m16n8k16.row.col.f32.bf16.bf16.f32 "
        "{%0,%1,%2,%3}, {%4,%5,%6,%7}, {%8,%9}, {%0,%1,%2,%3};"
        : "+f"(c[0]), "+f"(c[1]), "+f"(c[2]), "+f"(c[3])
        : "r"(a[0]), "r"(a[1]), "r"(a[2]), "r"(a[3]), "r"(b[0]), "r"(b[1]));
}

// ---------------------------------------------------------------------------
// Kernel A: precompute U_t[s,r] = sum_f c_f(t) Wr[f*S+s, r]
// ---------------------------------------------------------------------------
__global__ void precompute_U(const float* __restrict__ Wr,
                             const float* __restrict__ phases) {
    int t = blockIdx.x + 1;
    __shared__ float c[FF];
    if (threadIdx.x < FF) {
        float f = (float)threadIdx.x;
        float ang = (TWO_PI / (float)TT) * (float)t * f + TWO_PI * phases[threadIdx.x];
        c[threadIdx.x] = cosf(ang) * (1.0f / (float)TT);
    }
    __syncthreads();
    float* Udst = g_U + (size_t)(t - 1) * (SS * RR);
    for (int idx = threadIdx.x; idx < SS * RR; idx += blockDim.x) {
        int s = idx >> 6, r = idx & 63;
        float acc = 0.f;
#pragma unroll
        for (int f = 0; f < FF; ++f)
            acc += c[f] * Wr[(f * SS + s) * RR + r];
        Udst[idx] = acc;
    }
}

// ---------------------------------------------------------------------------
// Kernel A2: Wo^T hi/lo bf16 (tiled transpose; result is N-major)
// ---------------------------------------------------------------------------
__global__ void make_WoT(const float* __restrict__ Wo) {
    __shared__ float tile[32][33];
    const int tx = threadIdx.x, ty = threadIdx.y;
    const int gx = blockIdx.x * 32;   // n
    const int gy = blockIdx.y * 32;   // k
#pragma unroll
    for (int i = 0; i < 32; i += 8)
        tile[ty + i][tx] = Wo[(size_t)(gy + ty + i) * NTOT + gx + tx];
    __syncthreads();
#pragma unroll
    for (int i = 0; i < 32; i += 8) {
        float v = tile[tx][ty + i];                    // Wo[gy+tx][gx+ty+i]
        int n = gx + ty + i, k = gy + tx;
        __nv_bfloat16 h = __float2bfloat16(v);
        float lo = v - __bfloat162float(h);
        g_Bhi[(size_t)n * KTOT + k] = h;
        g_Blo[(size_t)n * KTOT + k] = __float2bfloat16(lo);
    }
}

// ---------------------------------------------------------------------------
// Kernel B: sequential recurrence; stores states as bf16 hi/lo
// ---------------------------------------------------------------------------
__global__ __launch_bounds__(256, 1)
void fru_recurrence(const float* __restrict__ x,
                    const float* __restrict__ Ws,
                    const float* __restrict__ bs,
                    const float* __restrict__ br,
                    const float* __restrict__ Wr,
                    const float* __restrict__ phases) {
    __shared__ __align__(16) float sU[2][SS * RR];
    __shared__ __align__(16) float sx[2][DD];
    __shared__ float sstate[STATE];
    __shared__ float sP[RR], sP0[RR], sstats[SS], srecur[RR];
    __shared__ float sredA[4 * 64], sredB[4 * 64];
    __shared__ float sc[FF], sph2[FF], sbr[RR], sbs[SS];

    const int tid  = threadIdx.x;
    const int lane = tid & 63;
    const int grp  = tid >> 6;
    const int b    = blockIdx.x;

    float wsr[48];
#pragma unroll
    for (int kk = 0; kk < 48; ++kk)
        wsr[kk] = Ws[(grp * 48 + kk) * SS + lane];
    float wr0r[16];
#pragma unroll
    for (int ss = 0; ss < 16; ++ss)
        wr0r[ss] = Wr[(grp * 16 + ss) * RR + lane];

    for (int i = tid; i < STATE; i += 256) sstate[i] = 0.f;
    if (tid < RR) { sP[tid] = 0.f; sP0[tid] = 0.f; sbr[tid] = br[tid]; }
    if (tid < SS) { sbs[tid] = bs[tid]; }
    if (tid < FF) { sph2[tid] = TWO_PI * phases[tid]; }

    {
        const float* Usrc = g_U;
#pragma unroll
        for (int q = 0; q < 4; ++q) {
            int i = tid + q * 256;
            __pipeline_memcpy_async(&sU[0][i * 4], &Usrc[i * 4], 16);
        }
        if (tid < 32)
            __pipeline_memcpy_async(&sx[0][tid * 4],
                                    x + ((size_t)b * TT) * DD + tid * 4, 16);
        __pipeline_commit();
    }

    const float invL  = 1.0f / (float)TT;
    const float wbase = TWO_PI / (float)TT;

    for (int t = 1; t <= TT; ++t) {
        const int cur = (t - 1) & 1;
        const int nxt = cur ^ 1;

        __pipeline_wait_prior(0);
        __syncthreads();

        if (t < TT) {
            const float* Usrc = g_U + (size_t)t * (SS * RR);
#pragma unroll
            for (int q = 0; q < 4; ++q) {
                int i = tid + q * 256;
                __pipeline_memcpy_async(&sU[nxt][i * 4], &Usrc[i * 4], 16);
            }
            if (tid < 32)
                __pipeline_memcpy_async(&sx[nxt][tid * 4],
                                        x + ((size_t)b * TT + t) * DD + tid * 4, 16);
            __pipeline_commit();
        }

        if (tid < FF) {
            float fv = (float)tid;
            sc[tid] = invL * cosf(wbase * (float)t * fv + sph2[tid]);
        }
        if (tid < RR) {
            float v = sP[tid] + sbr[tid];
            srecur[tid] = gelu_exact(v);
        }
        __syncthreads();

        {
            float a0 = 0.f, a1 = 0.f, a2 = 0.f, a3 = 0.f;
            const int k0 = grp * 48;
#pragma unroll
            for (int kk = 0; kk < 48; ++kk) {
                int k = k0 + kk;
                float v = (k < DD) ? sx[cur][k] : srecur[k - DD];
                float p = v * wsr[kk];
                if ((kk & 3) == 0) a0 += p;
                else if ((kk & 3) == 1) a1 += p;
                else if ((kk & 3) == 2) a2 += p;
                else a3 += p;
            }
            sredA[grp * 64 + lane] = (a0 + a1) + (a2 + a3);
        }
        __syncthreads();

        if (tid < SS) {
            float v = sredA[tid] + sredA[64 + tid] + sredA[128 + tid] +
                      sredA[192 + tid] + sbs[tid];
            sstats[tid] = gelu_exact(v);
        }
        __syncthreads();

        {
            const size_t outbase = ((size_t)b * TT + (t - 1)) * STATE;
#pragma unroll
            for (int q = 0; q < 4; ++q) {
                int i = tid + q * 256;
                int f = i >> 6, s = i & 63;
                float prev = (f == 0) ? 0.f : sstate[i];
                float ns = prev + sc[f] * sstats[s];
                sstate[i] = ns;
                __nv_bfloat16 h = __float2bfloat16(ns);
                g_Ahi[outbase + i] = h;
                g_Alo[outbase + i] = __float2bfloat16(ns - __bfloat162float(h));
            }
        }

        {
            float a1 = 0.f, b1 = 0.f, a2 = 0.f, b2 = 0.f;
            const int s0 = grp * 16;
#pragma unroll
            for (int ss = 0; ss < 16; ++ss) {
                float sv = sstats[s0 + ss];
                float u  = sU[cur][(s0 + ss) * RR + lane];
                if (ss & 1) { a1 += sv * u; b1 += sv * wr0r[ss]; }
                else        { a2 += sv * u; b2 += sv * wr0r[ss]; }
            }
            sredA[grp * 64 + lane] = a1 + a2;
            sredB[grp * 64 + lane] = b1 + b2;
        }
        __syncthreads();

        if (tid < RR) {
            float su = sredA[tid] + sredA[64 + tid] + sredA[128 + tid] + sredA[192 + tid];
            float sw = sredB[tid] + sredB[64 + tid] + sredB[128 + tid] + sredB[192 + tid];
            float np = sP[tid] - sP0[tid] + su;
            sP[tid]  = np;
            sP0[tid] = sc[0] * sw;
        }
    }
}

// ---------------------------------------------------------------------------
// Kernel C: out = gelu(states @ Wo + bo) via mma.sync bf16 split (HMMA).
// BM=128, BN=128, BK=32, 8 warps (4M x 2N), warp tile 32x64.
// 2-stage cp.async, 80KB smem, __launch_bounds__(256,2) -> 2 CTAs/SM.
// D = Ahi*Bhi + Ahi*Blo + Alo*Bhi (fp32 accumulate in registers).
// ---------------------------------------------------------------------------
#define BM 128
#define BN 128
#define BKH 32
#define NITER (KTOT / BKH)     // 32
#define NSTAGE 2
#define ROWH 40                               // padded row stride in halves (80B)
#define BUFB (128 * ROWH * 2)                 // 10240 B per matrix buffer
#define STAGEB (4 * BUFB)                     // 40960 B per stage
#define GEMM_SMEM (NSTAGE * STAGEB)           // 81920 B

#define LOAD_STAGE(step) do {                                               \
    char* st = smem + ((step) & 1) * STAGEB;                                \
    const int k0_ = (step) * BKH;                                           \
    _Pragma("unroll")                                                       \
    for (int q = 0; q < 2; ++q) {                                           \
        int idx = tid + q * 256;                                            \
        int r = idx >> 2, cc = idx & 3;                                     \
        int doff = (r * ROWH + cc * 8) * 2;                                 \
        size_t so = (size_t)r * KTOT + k0_ + cc * 8;                        \
        __pipeline_memcpy_async(st + doff,            Ah + so, 16);         \
        __pipeline_memcpy_async(st + BUFB + doff,     Al + so, 16);         \
        __pipeline_memcpy_async(st + 2 * BUFB + doff, Bh + so, 16);         \
        __pipeline_memcpy_async(st + 3 * BUFB + doff, Bl + so, 16);         \
    }                                                                       \
    __pipeline_commit();                                                    \
} while (0)

__global__ __launch_bounds__(256, 2)
void out_gemm_mma(const float* __restrict__ bo, float* __restrict__ out) {
    extern __shared__ __align__(128) char smem[];
    const uint32_t sbase = smem_u32(smem);
    const int tid  = threadIdx.x;
    const int lane = tid & 31;
    const int wid  = tid >> 5;
    const int wm   = wid & 3;       // 0..3 (M)
    const int wn   = wid >> 2;      // 0..1 (N)
    const int mBase = blockIdx.y * BM;
    const int nBase = blockIdx.x * BN;

    const __nv_bfloat16* Ah = g_Ahi + (size_t)mBase * KTOT;
    const __nv_bfloat16* Al = g_Alo + (size_t)mBase * KTOT;
    const __nv_bfloat16* Bh = g_Bhi + (size_t)nBase * KTOT;
    const __nv_bfloat16* Bl = g_Blo + (size_t)nBase * KTOT;

    // ldmatrix per-lane base offsets (bytes within a buffer)
    const int q = lane >> 3;
    // A quadrants: q0:(m,k0) q1:(m+8,k0) q2:(m,k8) q3:(m+8,k8)
    const uint32_t aoff = ((wm * 32 + (q & 1) * 8 + (lane & 7)) * ROWH + (q >> 1) * 8) * 2;
    // B quadrants: q0:(n,k0) q1:(n,k8) q2:(n+8,k0) q3:(n+8,k8)
    const uint32_t boff = ((wn * 64 + (q >> 1) * 8 + (lane & 7)) * ROWH + (q & 1) * 8) * 2;

    float acc[2][8][4];
#pragma unroll
    for (int i = 0; i < 2; ++i)
#pragma unroll
        for (int j = 0; j < 8; ++j)
#pragma unroll
            for (int v = 0; v < 4; ++v) acc[i][j][v] = 0.f;

    LOAD_STAGE(0);

    for (int i = 0; i < NITER; ++i) {
        __pipeline_wait_prior(0);
        __syncthreads();
        if (i + 1 < NITER) LOAD_STAGE(i + 1);

        const uint32_t sb = sbase + (uint32_t)(i & 1) * STAGEB;
#pragma unroll
        for (int ks = 0; ks < 2; ++ks) {
            uint32_t ahi[2][4], alo[2][4];
            ldsm4(ahi[0], sb + aoff + ks * 32);
            ldsm4(ahi[1], sb + aoff + 16 * ROWH * 2 + ks * 32);
            ldsm4(alo[0], sb + BUFB + aoff + ks * 32);
            ldsm4(alo[1], sb + BUFB + aoff + 16 * ROWH * 2 + ks * 32);
#pragma unroll
            for (int nt = 0; nt < 4; ++nt) {
                uint32_t bhi[4], blo[4];
                ldsm4(bhi, sb + 2 * BUFB + boff + nt * 16 * ROWH * 2 + ks * 32);
                ldsm4(blo, sb + 3 * BUFB + boff + nt * 16 * ROWH * 2 + ks * 32);
#pragma unroll
                for (int mt = 0; mt < 2; ++mt) {
#pragma unroll
                    for (int sub = 0; sub < 2; ++sub) {
                        float* c = acc[mt][nt * 2 + sub];
                        mma16816(c, ahi[mt], bhi + 2 * sub);
                        mma16816(c, ahi[mt], blo + 2 * sub);
                        mma16816(c, alo[mt], bhi + 2 * sub);
                    }
                }
            }
        }
    }

    // Epilogue: +bias, exact gelu, store float2 pairs
    const int mrow = lane >> 2;
    const int ncol = (lane & 3) * 2;
#pragma unroll
    for (int mt = 0; mt < 2; ++mt) {
        const int m0 = mBase + wm * 32 + mt * 16 + mrow;
#pragma unroll
        for (int nt8 = 0; nt8 < 8; ++nt8) {
            const int n0 = nBase + wn * 64 + nt8 * 8 + ncol;
            const float b0 = __ldg(bo + n0), b1 = __ldg(bo + n0 + 1);
            const float* c = acc[mt][nt8];
            float2 v0 = {gelu_exact(c[0] + b0), gelu_exact(c[1] + b1)};
            float2 v1 = {gelu_exact(c[2] + b0), gelu_exact(c[3] + b1)};
            *(float2*)(out + (size_t)m0 * NTOT + n0)       = v0;
            *(float2*)(out + (size_t)(m0 + 8) * NTOT + n0) = v1;
        }
    }
}

// ---------------------------------------------------------------------------
extern "C" void kernel_launch(void* const* d_in, const int* in_sizes, int n_in,
                              void* d_out, int out_size) {
    const float* x   = (const float*)d_in[0];  // (B,T,D)
    const float* Wr  = (const float*)d_in[1];  // (STATE,R)
    const float* br  = (const float*)d_in[2];  // (R,)
    const float* Ws  = (const float*)d_in[3];  // (D+R,S)
    const float* bs  = (const float*)d_in[4];  // (S,)
    const float* Wo  = (const float*)d_in[5];  // (STATE,STATE)
    const float* bo  = (const float*)d_in[6];  // (STATE,)
    const float* ph  = (const float*)d_in[7];  // (1,F,1)
    float* out = (float*)d_out;

    cudaFuncSetAttribute(out_gemm_mma, cudaFuncAttributeMaxDynamicSharedMemorySize, GEMM_SMEM);

    precompute_U<<<TT, 256>>>(Wr, ph);
    make_WoT<<<dim3(32, 32), dim3(32, 8)>>>(Wo);
    fru_recurrence<<<BB, 256>>>(x, Ws, bs, br, Wr, ph);
    out_gemm_mma<<<dim3(NTOT / BN, MTOT / BM), 256, GEMM_SMEM>>>(bo, out);
}

// round 5
// speedup vs baseline: 1.8464x; 1.1833x over previous
#include <cuda_runtime.h>
#include <cuda_pipeline.h>
#include <cuda_bf16.h>
#include <math.h>
#include <stdint.h>

#define BB    32
#define TT    2048
#define DD    128
#define FF    16
#define SS    64
#define RR    64
#define STATE 1024
#define TWO_PI 6.28318530717958647692f

#define MTOT  (BB * TT)      // 65536 GEMM rows
#define KTOT  1024
#define NTOT  1024

// ---------------- scratch (__device__ globals; no allocation allowed) -------
__device__ float         g_U[TT * SS * RR];            // 32 MB
__device__ __nv_bfloat16 g_Ahi[(size_t)MTOT * KTOT];   // 128 MB  states hi
__device__ __nv_bfloat16 g_Alo[(size_t)MTOT * KTOT];   // 128 MB  states lo
__device__ __nv_bfloat16 g_Bhi[(size_t)NTOT * KTOT];   // 2 MB    Wo^T hi (N-major)
__device__ __nv_bfloat16 g_Blo[(size_t)NTOT * KTOT];   // 2 MB    Wo^T lo (N-major)
__device__ int           g_progress[BB];               // steps completed per batch

__device__ __forceinline__ float gelu_exact(float v) { return v * normcdff(v); }

__device__ __forceinline__ uint32_t smem_u32(const void* p) {
    uint32_t a;
    asm("{ .reg .u64 t; cvta.to.shared.u64 t, %1; cvt.u32.u64 %0, t; }" : "=r"(a) : "l"(p));
    return a;
}
__device__ __forceinline__ void ldsm4(uint32_t* r, uint32_t addr) {
    asm volatile("ldmatrix.sync.aligned.m8n8.x4.shared.b16 {%0,%1,%2,%3}, [%4];"
                 : "=r"(r[0]), "=r"(r[1]), "=r"(r[2]), "=r"(r[3]) : "r"(addr));
}
__device__ __forceinline__ void mma16816(float* c, const uint32_t* a, const uint32_t* b) {
    asm volatile(
        "mma.sync.aligned.m16n8k16.row.col.f32.bf16.bf16.f32 "
        "{%0,%1,%2,%3}, {%4,%5,%6,%7}, {%8,%9}, {%0,%1,%2,%3};"
        : "+f"(c[0]), "+f"(c[1]), "+f"(c[2]), "+f"(c[3])
        : "r"(a[0]), "r"(a[1]), "r"(a[2]), "r"(a[3]), "r"(b[0]), "r"(b[1]));
}

// ---------------------------------------------------------------------------
// Kernel A: precompute U_t[s,r] = sum_f c_f(t) Wr[f*S+s, r]; also resets progress
// ---------------------------------------------------------------------------
__global__ void precompute_U(const float* __restrict__ Wr,
                             const float* __restrict__ phases) {
    int t = blockIdx.x + 1;
    if (blockIdx.x == 0 && threadIdx.x < BB) g_progress[threadIdx.x] = 0;
    __shared__ float c[FF];
    if (threadIdx.x < FF) {
        float f = (float)threadIdx.x;
        float ang = (TWO_PI / (float)TT) * (float)t * f + TWO_PI * phases[threadIdx.x];
        c[threadIdx.x] = cosf(ang) * (1.0f / (float)TT);
    }
    __syncthreads();
    float* Udst = g_U + (size_t)(t - 1) * (SS * RR);
    for (int idx = threadIdx.x; idx < SS * RR; idx += blockDim.x) {
        int s = idx >> 6, r = idx & 63;
        float acc = 0.f;
#pragma unroll
        for (int f = 0; f < FF; ++f)
            acc += c[f] * Wr[(f * SS + s) * RR + r];
        Udst[idx] = acc;
    }
}

// ---------------------------------------------------------------------------
// Kernel A2: Wo^T hi/lo bf16 (tiled transpose; result is N-major)
// ---------------------------------------------------------------------------
__global__ void make_WoT(const float* __restrict__ Wo) {
    __shared__ float tile[32][33];
    const int tx = threadIdx.x, ty = threadIdx.y;
    const int gx = blockIdx.x * 32;   // n
    const int gy = blockIdx.y * 32;   // k
#pragma unroll
    for (int i = 0; i < 32; i += 8)
        tile[ty + i][tx] = Wo[(size_t)(gy + ty + i) * NTOT + gx + tx];
    __syncthreads();
#pragma unroll
    for (int i = 0; i < 32; i += 8) {
        float v = tile[tx][ty + i];
        int n = gx + ty + i, k = gy + tx;
        __nv_bfloat16 h = __float2bfloat16(v);
        float lo = v - __bfloat162float(h);
        g_Bhi[(size_t)n * KTOT + k] = h;
        g_Blo[(size_t)n * KTOT + k] = __float2bfloat16(lo);
    }
}

// ---------------------------------------------------------------------------
// Fused kernel smem layouts (union over one 80KB dynamic buffer)
// ---------------------------------------------------------------------------
#define BM 128
#define BN 128
#define BKH 32
#define NITER (KTOT / BKH)     // 32
#define ROWH 40                // padded row stride in halves (80B)
#define BUFB (128 * ROWH * 2)  // 10240 B per matrix buffer
#define STAGEB (4 * BUFB)      // 40960 B per stage
#define GEMM_SMEM (2 * STAGEB) // 81920 B

struct RecSmem {
    float sU[2][SS * RR];
    float sx[2][DD];
    float sstate[STATE];
    float sP[RR], sP0[RR], sstats[SS], srecur[RR];
    float sredA[256], sredB[256];
    float sc[FF], sph2[FF], sbr[RR], sbs[SS];
};

// ---------------------------------------------------------------------------
// Recurrence body (producer). One CTA per batch; publishes every 128 steps.
// ---------------------------------------------------------------------------
__device__ void recurrence_body(char* smraw,
                                const float* __restrict__ x,
                                const float* __restrict__ Ws,
                                const float* __restrict__ bs,
                                const float* __restrict__ br,
                                const float* __restrict__ Wr,
                                const float* __restrict__ phases) {
    RecSmem* sm = (RecSmem*)smraw;
    const int tid  = threadIdx.x;
    const int lane = tid & 63;
    const int grp  = tid >> 6;
    const int b    = blockIdx.x;

    float wsr[48];
#pragma unroll
    for (int kk = 0; kk < 48; ++kk)
        wsr[kk] = Ws[(grp * 48 + kk) * SS + lane];
    float wr0r[16];
#pragma unroll
    for (int ss = 0; ss < 16; ++ss)
        wr0r[ss] = Wr[(grp * 16 + ss) * RR + lane];

    for (int i = tid; i < STATE; i += 256) sm->sstate[i] = 0.f;
    if (tid < RR) { sm->sP[tid] = 0.f; sm->sP0[tid] = 0.f; sm->sbr[tid] = br[tid]; }
    if (tid < SS) { sm->sbs[tid] = bs[tid]; }
    if (tid < FF) { sm->sph2[tid] = TWO_PI * phases[tid]; }

    {
        const float* Usrc = g_U;
#pragma unroll
        for (int q = 0; q < 4; ++q) {
            int i = tid + q * 256;
            __pipeline_memcpy_async(&sm->sU[0][i * 4], &Usrc[i * 4], 16);
        }
        if (tid < 32)
            __pipeline_memcpy_async(&sm->sx[0][tid * 4],
                                    x + ((size_t)b * TT) * DD + tid * 4, 16);
        __pipeline_commit();
    }

    const float invL  = 1.0f / (float)TT;
    const float wbase = TWO_PI / (float)TT;

    for (int t = 1; t <= TT; ++t) {
        const int cur = (t - 1) & 1;
        const int nxt = cur ^ 1;

        __pipeline_wait_prior(0);
        __syncthreads();

        if (t < TT) {
            const float* Usrc = g_U + (size_t)t * (SS * RR);
#pragma unroll
            for (int q = 0; q < 4; ++q) {
                int i = tid + q * 256;
                __pipeline_memcpy_async(&sm->sU[nxt][i * 4], &Usrc[i * 4], 16);
            }
            if (tid < 32)
                __pipeline_memcpy_async(&sm->sx[nxt][tid * 4],
                                        x + ((size_t)b * TT + t) * DD + tid * 4, 16);
            __pipeline_commit();
        }

        if (tid < FF) {
            float fv = (float)tid;
            sm->sc[tid] = invL * cosf(wbase * (float)t * fv + sm->sph2[tid]);
        }
        if (tid < RR) {
            float v = sm->sP[tid] + sm->sbr[tid];
            sm->srecur[tid] = gelu_exact(v);
        }
        __syncthreads();

        {
            float a0 = 0.f, a1 = 0.f, a2 = 0.f, a3 = 0.f;
            const int k0 = grp * 48;
#pragma unroll
            for (int kk = 0; kk < 48; ++kk) {
                int k = k0 + kk;
                float v = (k < DD) ? sm->sx[cur][k] : sm->srecur[k - DD];
                float p = v * wsr[kk];
                if ((kk & 3) == 0) a0 += p;
                else if ((kk & 3) == 1) a1 += p;
                else if ((kk & 3) == 2) a2 += p;
                else a3 += p;
            }
            sm->sredA[grp * 64 + lane] = (a0 + a1) + (a2 + a3);
        }
        __syncthreads();

        if (tid < SS) {
            float v = sm->sredA[tid] + sm->sredA[64 + tid] + sm->sredA[128 + tid] +
                      sm->sredA[192 + tid] + sm->sbs[tid];
            sm->sstats[tid] = gelu_exact(v);
        }
        __syncthreads();

        {
            const size_t outbase = ((size_t)b * TT + (t - 1)) * STATE;
#pragma unroll
            for (int q = 0; q < 4; ++q) {
                int i = tid + q * 256;
                int f = i >> 6, s = i & 63;
                float prev = (f == 0) ? 0.f : sm->sstate[i];
                float ns = prev + sm->sc[f] * sm->sstats[s];
                sm->sstate[i] = ns;
                __nv_bfloat16 h = __float2bfloat16(ns);
                g_Ahi[outbase + i] = h;
                g_Alo[outbase + i] = __float2bfloat16(ns - __bfloat162float(h));
            }
        }

        {
            float a1 = 0.f, b1 = 0.f, a2 = 0.f, b2 = 0.f;
            const int s0 = grp * 16;
#pragma unroll
            for (int ss = 0; ss < 16; ++ss) {
                float sv = sm->sstats[s0 + ss];
                float u  = sm->sU[cur][(s0 + ss) * RR + lane];
                if (ss & 1) { a1 += sv * u; b1 += sv * wr0r[ss]; }
                else        { a2 += sv * u; b2 += sv * wr0r[ss]; }
            }
            sm->sredA[grp * 64 + lane] = a1 + a2;
            sm->sredB[grp * 64 + lane] = b1 + b2;
        }
        __syncthreads();                         // all g_A writes for step t done above

        if (tid < RR) {
            float su = sm->sredA[tid] + sm->sredA[64 + tid] + sm->sredA[128 + tid] + sm->sredA[192 + tid];
            float sw = sm->sredB[tid] + sm->sredB[64 + tid] + sm->sredB[128 + tid] + sm->sredB[192 + tid];
            float np = sm->sP[tid] - sm->sP0[tid] + su;
            sm->sP[tid]  = np;
            sm->sP0[tid] = sm->sc[0] * sw;
        }
        // publish progress every 128 steps (CG grid-sync pattern: bar -> fence -> store)
        if ((t & 127) == 0 && tid == 64) {
            __threadfence();
            *(volatile int*)&g_progress[b] = t;
        }
    }
}

// ---------------------------------------------------------------------------
// GEMM body (consumer). Tile id ordered t-chunk-major so CTA dispatch order
// matches data production order.
// ---------------------------------------------------------------------------
#define LOAD_STAGE(step) do {                                               \
    char* st = smraw + ((step) & 1) * STAGEB;                               \
    const int k0_ = (step) * BKH;                                           \
    _Pragma("unroll")                                                       \
    for (int q = 0; q < 2; ++q) {                                           \
        int idx = tid + q * 256;                                            \
        int r = idx >> 2, cc = idx & 3;                                     \
        int doff = (r * ROWH + cc * 8) * 2;                                 \
        size_t so = (size_t)r * KTOT + k0_ + cc * 8;                        \
        __pipeline_memcpy_async(st + doff,            Ah + so, 16);         \
        __pipeline_memcpy_async(st + BUFB + doff,     Al + so, 16);         \
        __pipeline_memcpy_async(st + 2 * BUFB + doff, Bh + so, 16);         \
        __pipeline_memcpy_async(st + 3 * BUFB + doff, Bl + so, 16);         \
    }                                                                       \
    __pipeline_commit();                                                    \
} while (0)

__device__ void gemm_body(char* smraw,
                          const float* __restrict__ bo, float* __restrict__ out) {
    const uint32_t sbase = smem_u32(smraw);
    const int tid  = threadIdx.x;
    const int lane = tid & 31;
    const int wid  = tid >> 5;
    const int wm   = wid & 3;
    const int wn   = wid >> 2;

    const int gi     = blockIdx.x - BB;
    const int tchunk = gi >> 8;          // 0..15
    const int rem    = gi & 255;
    const int b      = rem >> 3;         // 0..31
    const int nt     = rem & 7;          // 0..7
    const int mBase  = b * TT + tchunk * BM;
    const int nBase  = nt * BN;

    // Wait until this batch has produced our 128 rows.
    if (tid == 0) {
        const int need = (tchunk + 1) * BM;
        while (*(volatile int*)&g_progress[b] < need) __nanosleep(200);
        __threadfence();
    }
    __syncthreads();

    const __nv_bfloat16* Ah = g_Ahi + (size_t)mBase * KTOT;
    const __nv_bfloat16* Al = g_Alo + (size_t)mBase * KTOT;
    const __nv_bfloat16* Bh = g_Bhi + (size_t)nBase * KTOT;
    const __nv_bfloat16* Bl = g_Blo + (size_t)nBase * KTOT;

    const int q = lane >> 3;
    const uint32_t aoff = ((wm * 32 + (q & 1) * 8 + (lane & 7)) * ROWH + (q >> 1) * 8) * 2;
    const uint32_t boff = ((wn * 64 + (q >> 1) * 8 + (lane & 7)) * ROWH + (q & 1) * 8) * 2;

    float acc[2][8][4];
#pragma unroll
    for (int i = 0; i < 2; ++i)
#pragma unroll
        for (int j = 0; j < 8; ++j)
#pragma unroll
            for (int v = 0; v < 4; ++v) acc[i][j][v] = 0.f;

    LOAD_STAGE(0);

    for (int i = 0; i < NITER; ++i) {
        __pipeline_wait_prior(0);
        __syncthreads();
        if (i + 1 < NITER) LOAD_STAGE(i + 1);

        const uint32_t sb = sbase + (uint32_t)(i & 1) * STAGEB;
#pragma unroll
        for (int ks = 0; ks < 2; ++ks) {
            uint32_t ahi[2][4], alo[2][4];
            ldsm4(ahi[0], sb + aoff + ks * 32);
            ldsm4(ahi[1], sb + aoff + 16 * ROWH * 2 + ks * 32);
            ldsm4(alo[0], sb + BUFB + aoff + ks * 32);
            ldsm4(alo[1], sb + BUFB + aoff + 16 * ROWH * 2 + ks * 32);
#pragma unroll
            for (int nt4 = 0; nt4 < 4; ++nt4) {
                uint32_t bhi[4], blo[4];
                ldsm4(bhi, sb + 2 * BUFB + boff + nt4 * 16 * ROWH * 2 + ks * 32);
                ldsm4(blo, sb + 3 * BUFB + boff + nt4 * 16 * ROWH * 2 + ks * 32);
#pragma unroll
                for (int mt = 0; mt < 2; ++mt) {
#pragma unroll
                    for (int sub = 0; sub < 2; ++sub) {
                        float* c = acc[mt][nt4 * 2 + sub];
                        mma16816(c, ahi[mt], bhi + 2 * sub);
                        mma16816(c, ahi[mt], blo + 2 * sub);
                        mma16816(c, alo[mt], bhi + 2 * sub);
                    }
                }
            }
        }
    }

    const int mrow = lane >> 2;
    const int ncol = (lane & 3) * 2;
#pragma unroll
    for (int mt = 0; mt < 2; ++mt) {
        const int m0 = mBase + wm * 32 + mt * 16 + mrow;
#pragma unroll
        for (int nt8 = 0; nt8 < 8; ++nt8) {
            const int n0 = nBase + wn * 64 + nt8 * 8 + ncol;
            const float b0 = __ldg(bo + n0), b1 = __ldg(bo + n0 + 1);
            const float* c = acc[mt][nt8];
            float2 v0 = {gelu_exact(c[0] + b0), gelu_exact(c[1] + b1)};
            float2 v1 = {gelu_exact(c[2] + b0), gelu_exact(c[3] + b1)};
            *(float2*)(out + (size_t)m0 * NTOT + n0)       = v0;
            *(float2*)(out + (size_t)(m0 + 8) * NTOT + n0) = v1;
        }
    }
}

// ---------------------------------------------------------------------------
// Fused kernel: blockIdx < 32 -> recurrence (producer); else GEMM (consumer)
// ---------------------------------------------------------------------------
__global__ __launch_bounds__(256, 2)
void fru_fused(const float* __restrict__ x,
               const float* __restrict__ Ws,
               const float* __restrict__ bs,
               const float* __restrict__ br,
               const float* __restrict__ Wr,
               const float* __restrict__ phases,
               const float* __restrict__ bo,
               float* __restrict__ out) {
    extern __shared__ __align__(128) char smraw[];
    if (blockIdx.x < BB)
        recurrence_body(smraw, x, Ws, bs, br, Wr, phases);
    else
        gemm_body(smraw, bo, out);
}

// ---------------------------------------------------------------------------
extern "C" void kernel_launch(void* const* d_in, const int* in_sizes, int n_in,
                              void* d_out, int out_size) {
    const float* x   = (const float*)d_in[0];  // (B,T,D)
    const float* Wr  = (const float*)d_in[1];  // (STATE,R)
    const float* br  = (const float*)d_in[2];  // (R,)
    const float* Ws  = (const float*)d_in[3];  // (D+R,S)
    const float* bs  = (const float*)d_in[4];  // (S,)
    const float* Wo  = (const float*)d_in[5];  // (STATE,STATE)
    const float* bo  = (const float*)d_in[6];  // (STATE,)
    const float* ph  = (const float*)d_in[7];  // (1,F,1)
    float* out = (float*)d_out;

    cudaFuncSetAttribute(fru_fused, cudaFuncAttributeMaxDynamicSharedMemorySize, GEMM_SMEM);

    precompute_U<<<TT, 256>>>(Wr, ph);
    make_WoT<<<dim3(32, 32), dim3(32, 8)>>>(Wo);
    fru_fused<<<BB + (MTOT / BM) * (NTOT / BN), 256, GEMM_SMEM>>>(
        x, Ws, bs, br, Wr, ph, bo, out);
}

// round 6
// speedup vs baseline: 1.8507x; 1.0023x over previous
#include <cuda_runtime.h>
#include <cuda_pipeline.h>
#include <cuda_bf16.h>
#include <math.h>
#include <stdint.h>

#define BB    32
#define TT    2048
#define DD    128
#define FF    16
#define SS    64
#define RR    64
#define STATE 1024
#define TWO_PI 6.28318530717958647692f

#define MTOT  (BB * TT)      // 65536 GEMM rows
#define KTOT  1024
#define NTOT  1024

// ---------------- scratch (__device__ globals; no allocation allowed) -------
__device__ float         g_U[TT * SS * RR];            // 32 MB
__device__ __nv_bfloat16 g_Ahi[(size_t)MTOT * KTOT];   // 128 MB  states hi
__device__ __nv_bfloat16 g_Alo[(size_t)MTOT * KTOT];   // 128 MB  states lo
__device__ __nv_bfloat16 g_Bhi[(size_t)NTOT * KTOT];   // 2 MB    Wo^T hi (N-major)
__device__ __nv_bfloat16 g_Blo[(size_t)NTOT * KTOT];   // 2 MB    Wo^T lo (N-major)
__device__ int           g_progress[BB];               // steps completed per batch

__device__ __forceinline__ float gelu_exact(float v) { return v * normcdff(v); }

__device__ __forceinline__ uint32_t smem_u32(const void* p) {
    uint32_t a;
    asm("{ .reg .u64 t; cvta.to.shared.u64 t, %1; cvt.u32.u64 %0, t; }" : "=r"(a) : "l"(p));
    return a;
}
__device__ __forceinline__ void ldsm4(uint32_t* r, uint32_t addr) {
    asm volatile("ldmatrix.sync.aligned.m8n8.x4.shared.b16 {%0,%1,%2,%3}, [%4];"
                 : "=r"(r[0]), "=r"(r[1]), "=r"(r[2]), "=r"(r[3]) : "r"(addr));
}
__device__ __forceinline__ void mma16816(float* c, const uint32_t* a, const uint32_t* b) {
    asm volatile(
        "mma.sync.aligned.m16n8k16.row.col.f32.bf16.bf16.f32 "
        "{%0,%1,%2,%3}, {%4,%5,%6,%7}, {%8,%9}, {%0,%1,%2,%3};"
        : "+f"(c[0]), "+f"(c[1]), "+f"(c[2]), "+f"(c[3])
        : "r"(a[0]), "r"(a[1]), "r"(a[2]), "r"(a[3]), "r"(b[0]), "r"(b[1]));
}

// ---------------------------------------------------------------------------
// Kernel A: precompute U_t[s,r] = sum_f c_f(t) Wr[f*S+s, r]; also resets progress
// ---------------------------------------------------------------------------
__global__ void precompute_U(const float* __restrict__ Wr,
                             const float* __restrict__ phases) {
    int t = blockIdx.x + 1;
    if (blockIdx.x == 0 && threadIdx.x < BB) g_progress[threadIdx.x] = 0;
    __shared__ float c[FF];
    if (threadIdx.x < FF) {
        float f = (float)threadIdx.x;
        float ang = (TWO_PI / (float)TT) * (float)t * f + TWO_PI * phases[threadIdx.x];
        c[threadIdx.x] = cosf(ang) * (1.0f / (float)TT);
    }
    __syncthreads();
    float* Udst = g_U + (size_t)(t - 1) * (SS * RR);
    for (int idx = threadIdx.x; idx < SS * RR; idx += blockDim.x) {
        int s = idx >> 6, r = idx & 63;
        float acc = 0.f;
#pragma unroll
        for (int f = 0; f < FF; ++f)
            acc += c[f] * Wr[(f * SS + s) * RR + r];
        Udst[idx] = acc;
    }
}

// ---------------------------------------------------------------------------
// Kernel A2: Wo^T hi/lo bf16 (tiled transpose; result is N-major)
// ---------------------------------------------------------------------------
__global__ void make_WoT(const float* __restrict__ Wo) {
    __shared__ float tile[32][33];
    const int tx = threadIdx.x, ty = threadIdx.y;
    const int gx = blockIdx.x * 32;   // n
    const int gy = blockIdx.y * 32;   // k
#pragma unroll
    for (int i = 0; i < 32; i += 8)
        tile[ty + i][tx] = Wo[(size_t)(gy + ty + i) * NTOT + gx + tx];
    __syncthreads();
#pragma unroll
    for (int i = 0; i < 32; i += 8) {
        float v = tile[tx][ty + i];
        int n = gx + ty + i, k = gy + tx;
        __nv_bfloat16 h = __float2bfloat16(v);
        float lo = v - __bfloat162float(h);
        g_Bhi[(size_t)n * KTOT + k] = h;
        g_Blo[(size_t)n * KTOT + k] = __float2bfloat16(lo);
    }
}

// ---------------------------------------------------------------------------
// Fused kernel smem layouts (union over one 80KB dynamic buffer)
// ---------------------------------------------------------------------------
#define BM 128
#define BN 128
#define BKH 32
#define NITER (KTOT / BKH)     // 32
#define ROWH 40                // padded row stride in halves (80B)
#define BUFB (128 * ROWH * 2)  // 10240 B per matrix buffer
#define STAGEB (4 * BUFB)      // 40960 B per stage
#define GEMM_SMEM (2 * STAGEB) // 81920 B

struct RecSmem {
    float sU[2][SS * RR];
    float sx[2][DD];
    float sstate[STATE];
    float sP[RR], sP0[RR], sstats[SS], srecur[RR];
    float sredA[256], sredB[256];
    float sc[FF], sph2[FF], sbr[RR], sbs[SS];
};

// ---------------------------------------------------------------------------
// Recurrence body (producer). One CTA per batch; publishes every 128 steps.
// ---------------------------------------------------------------------------
__device__ void recurrence_body(char* smraw,
                                const float* __restrict__ x,
                                const float* __restrict__ Ws,
                                const float* __restrict__ bs,
                                const float* __restrict__ br,
                                const float* __restrict__ Wr,
                                const float* __restrict__ phases) {
    RecSmem* sm = (RecSmem*)smraw;
    const int tid  = threadIdx.x;
    const int lane = tid & 63;
    const int grp  = tid >> 6;
    const int b    = blockIdx.x;

    float wsr[48];
#pragma unroll
    for (int kk = 0; kk < 48; ++kk)
        wsr[kk] = Ws[(grp * 48 + kk) * SS + lane];
    float wr0r[16];
#pragma unroll
    for (int ss = 0; ss < 16; ++ss)
        wr0r[ss] = Wr[(grp * 16 + ss) * RR + lane];

    for (int i = tid; i < STATE; i += 256) sm->sstate[i] = 0.f;
    if (tid < RR) { sm->sP[tid] = 0.f; sm->sP0[tid] = 0.f; sm->sbr[tid] = br[tid]; }
    if (tid < SS) { sm->sbs[tid] = bs[tid]; }
    if (tid < FF) { sm->sph2[tid] = TWO_PI * phases[tid]; }

    {
        const float* Usrc = g_U;
#pragma unroll
        for (int q = 0; q < 4; ++q) {
            int i = tid + q * 256;
            __pipeline_memcpy_async(&sm->sU[0][i * 4], &Usrc[i * 4], 16);
        }
        if (tid < 32)
            __pipeline_memcpy_async(&sm->sx[0][tid * 4],
                                    x + ((size_t)b * TT) * DD + tid * 4, 16);
        __pipeline_commit();
    }

    const float invL  = 1.0f / (float)TT;
    const float wbase = TWO_PI / (float)TT;

    for (int t = 1; t <= TT; ++t) {
        const int cur = (t - 1) & 1;
        const int nxt = cur ^ 1;

        __pipeline_wait_prior(0);
        __syncthreads();

        if (t < TT) {
            const float* Usrc = g_U + (size_t)t * (SS * RR);
#pragma unroll
            for (int q = 0; q < 4; ++q) {
                int i = tid + q * 256;
                __pipeline_memcpy_async(&sm->sU[nxt][i * 4], &Usrc[i * 4], 16);
            }
            if (tid < 32)
                __pipeline_memcpy_async(&sm->sx[nxt][tid * 4],
                                        x + ((size_t)b * TT + t) * DD + tid * 4, 16);
            __pipeline_commit();
        }

        if (tid < FF) {
            float fv = (float)tid;
            sm->sc[tid] = invL * cosf(wbase * (float)t * fv + sm->sph2[tid]);
        }
        if (tid < RR) {
            float v = sm->sP[tid] + sm->sbr[tid];
            sm->srecur[tid] = gelu_exact(v);
        }
        __syncthreads();

        {
            float a0 = 0.f, a1 = 0.f, a2 = 0.f, a3 = 0.f;
            const int k0 = grp * 48;
#pragma unroll
            for (int kk = 0; kk < 48; ++kk) {
                int k = k0 + kk;
                float v = (k < DD) ? sm->sx[cur][k] : sm->srecur[k - DD];
                float p = v * wsr[kk];
                if ((kk & 3) == 0) a0 += p;
                else if ((kk & 3) == 1) a1 += p;
                else if ((kk & 3) == 2) a2 += p;
                else a3 += p;
            }
            sm->sredA[grp * 64 + lane] = (a0 + a1) + (a2 + a3);
        }
        __syncthreads();

        if (tid < SS) {
            float v = sm->sredA[tid] + sm->sredA[64 + tid] + sm->sredA[128 + tid] +
                      sm->sredA[192 + tid] + sm->sbs[tid];
            sm->sstats[tid] = gelu_exact(v);
        }
        __syncthreads();

        {
            const size_t outbase = ((size_t)b * TT + (t - 1)) * STATE;
#pragma unroll
            for (int q = 0; q < 4; ++q) {
                int i = tid + q * 256;
                int f = i >> 6, s = i & 63;
                float prev = (f == 0) ? 0.f : sm->sstate[i];
                float ns = prev + sm->sc[f] * sm->sstats[s];
                sm->sstate[i] = ns;
                __nv_bfloat16 h = __float2bfloat16(ns);
                g_Ahi[outbase + i] = h;
                g_Alo[outbase + i] = __float2bfloat16(ns - __bfloat162float(h));
            }
        }

        {
            float a1 = 0.f, b1 = 0.f, a2 = 0.f, b2 = 0.f;
            const int s0 = grp * 16;
#pragma unroll
            for (int ss = 0; ss < 16; ++ss) {
                float sv = sm->sstats[s0 + ss];
                float u  = sm->sU[cur][(s0 + ss) * RR + lane];
                if (ss & 1) { a1 += sv * u; b1 += sv * wr0r[ss]; }
                else        { a2 += sv * u; b2 += sv * wr0r[ss]; }
            }
            sm->sredA[grp * 64 + lane] = a1 + a2;
            sm->sredB[grp * 64 + lane] = b1 + b2;
        }
        __syncthreads();

        if (tid < RR) {
            float su = sm->sredA[tid] + sm->sredA[64 + tid] + sm->sredA[128 + tid] + sm->sredA[192 + tid];
            float sw = sm->sredB[tid] + sm->sredB[64 + tid] + sm->sredB[128 + tid] + sm->sredB[192 + tid];
            float np = sm->sP[tid] - sm->sP0[tid] + su;
            sm->sP[tid]  = np;
            sm->sP0[tid] = sm->sc[0] * sw;
        }
        if ((t & 127) == 0 && tid == 64) {
            __threadfence();
            *(volatile int*)&g_progress[b] = t;
        }
    }
}

// ---------------------------------------------------------------------------
// GEMM body (consumer). Hoisted ldsm addresses + term-major MMA ordering.
// ---------------------------------------------------------------------------
#define LOAD_STAGE(step) do {                                               \
    char* st = smraw + ((step) & 1) * STAGEB + doff;                        \
    const size_t so = (size_t)(step) * BKH;                                 \
    __pipeline_memcpy_async(st,            pAh + so, 16);                   \
    __pipeline_memcpy_async(st + BUFB,     pAl + so, 16);                   \
    __pipeline_memcpy_async(st + 2 * BUFB, pBh + so, 16);                   \
    __pipeline_memcpy_async(st + 3 * BUFB, pBl + so, 16);                   \
    char* st2 = st + D2OFF;                                                 \
    __pipeline_memcpy_async(st2,            pAh + so + S2OFF, 16);          \
    __pipeline_memcpy_async(st2 + BUFB,     pAl + so + S2OFF, 16);          \
    __pipeline_memcpy_async(st2 + 2 * BUFB, pBh + so + S2OFF, 16);          \
    __pipeline_memcpy_async(st2 + 3 * BUFB, pBl + so + S2OFF, 16);          \
    __pipeline_commit();                                                    \
} while (0)

#define D2OFF (64 * ROWH * 2)
#define S2OFF ((size_t)64 * KTOT)

__device__ void gemm_body(char* smraw,
                          const float* __restrict__ bo, float* __restrict__ out) {
    const uint32_t sbase = smem_u32(smraw);
    const int tid  = threadIdx.x;
    const int lane = tid & 31;
    const int wid  = tid >> 5;
    const int wm   = wid & 3;
    const int wn   = wid >> 2;

    const int gi     = blockIdx.x - BB;
    const int tchunk = gi >> 8;          // 0..15
    const int rem    = gi & 255;
    const int b      = rem >> 3;         // 0..31
    const int nt     = rem & 7;          // 0..7
    const int mBase  = b * TT + tchunk * BM;
    const int nBase  = nt * BN;

    if (tid == 0) {
        const int need = (tchunk + 1) * BM;
        while (*(volatile int*)&g_progress[b] < need) __nanosleep(256);
        __threadfence();
    }
    __syncthreads();

    // Per-thread cp.async bases (row r = tid>>2, col group cc = tid&3)
    const int r  = tid >> 2;
    const int cc = tid & 3;
    const int doff = (r * ROWH + cc * 8) * 2;
    const __nv_bfloat16* pAh = g_Ahi + (size_t)(mBase + r) * KTOT + cc * 8;
    const __nv_bfloat16* pAl = g_Alo + (size_t)(mBase + r) * KTOT + cc * 8;
    const __nv_bfloat16* pBh = g_Bhi + (size_t)(nBase + r) * KTOT + cc * 8;
    const __nv_bfloat16* pBl = g_Blo + (size_t)(nBase + r) * KTOT + cc * 8;

    // Hoisted ldmatrix addresses (stage 0); toggle by +=soff each iter.
    const int q = lane >> 3;
    const uint32_t aoff = ((wm * 32 + (q & 1) * 8 + (lane & 7)) * ROWH + (q >> 1) * 8) * 2;
    const uint32_t boff = ((wn * 64 + (q >> 1) * 8 + (lane & 7)) * ROWH + (q & 1) * 8) * 2;
    uint32_t adr[12];
    adr[0] = sbase + aoff;                       // A hi, mt0
    adr[1] = adr[0] + 16 * ROWH * 2;             // A hi, mt1
    adr[2] = sbase + BUFB + aoff;                // A lo, mt0
    adr[3] = adr[2] + 16 * ROWH * 2;             // A lo, mt1
#pragma unroll
    for (int n4 = 0; n4 < 4; ++n4) {
        adr[4 + n4] = sbase + 2 * BUFB + boff + n4 * 16 * ROWH * 2;  // B hi
        adr[8 + n4] = sbase + 3 * BUFB + boff + n4 * 16 * ROWH * 2;  // B lo
    }
    int soff = STAGEB;

    float acc[2][8][4];
#pragma unroll
    for (int i = 0; i < 2; ++i)
#pragma unroll
        for (int j = 0; j < 8; ++j)
#pragma unroll
            for (int v = 0; v < 4; ++v) acc[i][j][v] = 0.f;

    LOAD_STAGE(0);

    for (int i = 0; i < NITER; ++i) {
        __pipeline_wait_prior(0);
        __syncthreads();
        if (i + 1 < NITER) LOAD_STAGE(i + 1);

#pragma unroll
        for (int ks = 0; ks < 2; ++ks) {
            const uint32_t kso = ks * 32;
            uint32_t ahi[2][4], alo[2][4];
            ldsm4(ahi[0], adr[0] + kso);
            ldsm4(ahi[1], adr[1] + kso);
            ldsm4(alo[0], adr[2] + kso);
            ldsm4(alo[1], adr[3] + kso);
#pragma unroll
            for (int n4 = 0; n4 < 4; ++n4) {
                uint32_t bhi[4], blo[4];
                ldsm4(bhi, adr[4 + n4] + kso);
                ldsm4(blo, adr[8 + n4] + kso);
                float* c00 = acc[0][n4 * 2];
                float* c01 = acc[0][n4 * 2 + 1];
                float* c10 = acc[1][n4 * 2];
                float* c11 = acc[1][n4 * 2 + 1];
                // term-major: 4 independent MMAs per term
                mma16816(c00, ahi[0], bhi);
                mma16816(c01, ahi[0], bhi + 2);
                mma16816(c10, ahi[1], bhi);
                mma16816(c11, ahi[1], bhi + 2);
                mma16816(c00, ahi[0], blo);
                mma16816(c01, ahi[0], blo + 2);
                mma16816(c10, ahi[1], blo);
                mma16816(c11, ahi[1], blo + 2);
                mma16816(c00, alo[0], bhi);
                mma16816(c01, alo[0], bhi + 2);
                mma16816(c10, alo[1], bhi);
                mma16816(c11, alo[1], bhi + 2);
            }
        }
#pragma unroll
        for (int j = 0; j < 12; ++j) adr[j] += soff;
        soff = -soff;
    }

    const int mrow = lane >> 2;
    const int ncol = (lane & 3) * 2;
#pragma unroll
    for (int mt = 0; mt < 2; ++mt) {
        const int m0 = mBase + wm * 32 + mt * 16 + mrow;
#pragma unroll
        for (int nt8 = 0; nt8 < 8; ++nt8) {
            const int n0 = nBase + wn * 64 + nt8 * 8 + ncol;
            const float b0 = __ldg(bo + n0), b1 = __ldg(bo + n0 + 1);
            const float* c = acc[mt][nt8];
            float2 v0 = {gelu_exact(c[0] + b0), gelu_exact(c[1] + b1)};
            float2 v1 = {gelu_exact(c[2] + b0), gelu_exact(c[3] + b1)};
            *(float2*)(out + (size_t)m0 * NTOT + n0)       = v0;
            *(float2*)(out + (size_t)(m0 + 8) * NTOT + n0) = v1;
        }
    }
}

// ---------------------------------------------------------------------------
// Fused kernel: blockIdx < 32 -> recurrence (producer); else GEMM (consumer)
// ---------------------------------------------------------------------------
__global__ __launch_bounds__(256, 2)
void fru_fused(const float* __restrict__ x,
               const float* __restrict__ Ws,
               const float* __restrict__ bs,
               const float* __restrict__ br,
               const float* __restrict__ Wr,
               const float* __restrict__ phases,
               const float* __restrict__ bo,
               float* __restrict__ out) {
    extern __shared__ __align__(128) char smraw[];
    if (blockIdx.x < BB)
        recurrence_body(smraw, x, Ws, bs, br, Wr, phases);
    else
        gemm_body(smraw, bo, out);
}

// ---------------------------------------------------------------------------
extern "C" void kernel_launch(void* const* d_in, const int* in_sizes, int n_in,
                              void* d_out, int out_size) {
    const float* x   = (const float*)d_in[0];  // (B,T,D)
    const float* Wr  = (const float*)d_in[1];  // (STATE,R)
    const float* br  = (const float*)d_in[2];  // (R,)
    const float* Ws  = (const float*)d_in[3];  // (D+R,S)
    const float* bs  = (const float*)d_in[4];  // (S,)
    const float* Wo  = (const float*)d_in[5];  // (STATE,STATE)
    const float* bo  = (const float*)d_in[6];  // (STATE,)
    const float* ph  = (const float*)d_in[7];  // (1,F,1)
    float* out = (float*)d_out;

    cudaFuncSetAttribute(fru_fused, cudaFuncAttributeMaxDynamicSharedMemorySize, GEMM_SMEM);

    precompute_U<<<TT, 256>>>(Wr, ph);
    make_WoT<<<dim3(32, 32), dim3(32, 8)>>>(Wo);
    fru_fused<<<BB + (MTOT / BM) * (NTOT / BN), 256, GEMM_SMEM>>>(
        x, Ws, bs, br, Wr, ph, bo, out);
}